// round 4
// baseline (speedup 1.0000x reference)
#include <cuda_runtime.h>

#define NPTS 16384
#define NS   8192
#define KNB  10
#define R2   0.0625f
#define NGRP 256
#define GSZ  64
#define GDIM 8
#define NCELL (GDIM * GDIM * GDIM)
#define CPB  32

typedef unsigned long long ull;

// ---------------- global scratch (no allocation allowed) ----------------
__device__ __align__(16) float g_px[NPTS];   // original order SoA
__device__ __align__(16) float g_py[NPTS];
__device__ __align__(16) float g_pz[NPTS];
__device__ __align__(16) float g_sx[NPTS];   // spatially sorted SoA
__device__ __align__(16) float g_sy[NPTS];
__device__ __align__(16) float g_sz[NPTS];
__device__ __align__(16) int   g_sidx[NPTS]; // sorted slot -> original index
__device__ int g_cellcnt[NCELL];
__device__ int g_cellcur[NCELL];
__device__ float4 g_boxa[NGRP];              // {minx,miny,minz, FLT_MAX}
__device__ float4 g_boxb[NGRP];              // {maxx,maxy,maxz, 0}
__device__ float g_cx[NS], g_cy[NS], g_cz[NS];
__device__ int   g_src[NS * KNB];

// ---------------- packed f32x2 helpers (bit-exact IEEE RN per lane) ------
__device__ __forceinline__ ull f2_add(ull a, ull b) {
    ull r; asm("add.rn.f32x2 %0, %1, %2;" : "=l"(r) : "l"(a), "l"(b)); return r;
}
__device__ __forceinline__ ull f2_mul(ull a, ull b) {
    ull r; asm("mul.rn.f32x2 %0, %1, %2;" : "=l"(r) : "l"(a), "l"(b)); return r;
}
__device__ __forceinline__ ull pack2(unsigned lo, unsigned hi) {
    ull r; asm("mov.b64 %0, {%1, %2};" : "=l"(r) : "r"(lo), "r"(hi)); return r;
}
__device__ __forceinline__ void unpack2(unsigned &lo, unsigned &hi, ull v) {
    asm("mov.b64 {%0, %1}, %2;" : "=r"(lo), "=r"(hi) : "l"(v));
}
__device__ __forceinline__ ull umax64(ull a, ull b) { return a > b ? a : b; }
__device__ __forceinline__ ull umin64(ull a, ull b) { return a < b ? a : b; }
__device__ __forceinline__ int cell_of(float x, float y, float z) {
    int cx = min(GDIM - 1, (int)(x * (float)GDIM));
    int cy = min(GDIM - 1, (int)(y * (float)GDIM));
    int cz = min(GDIM - 1, (int)(z * (float)GDIM));
    return (cz * GDIM + cy) * GDIM + cx;
}

// ---------------- K0: AoS -> SoA + zero counters ----------------
__global__ void prep_kernel(const float* __restrict__ pos) {
    int i = blockIdx.x * blockDim.x + threadIdx.x;
    if (i < NCELL) g_cellcnt[i] = 0;
    if (i < NPTS) {
        g_px[i] = pos[3 * i + 0];
        g_py[i] = pos[3 * i + 1];
        g_pz[i] = pos[3 * i + 2];
    }
}
// ---------------- K0b: histogram ----------------
__global__ void hist_kernel() {
    int i = blockIdx.x * blockDim.x + threadIdx.x;
    if (i < NPTS) atomicAdd(&g_cellcnt[cell_of(g_px[i], g_py[i], g_pz[i])], 1);
}
// ---------------- K0c: exclusive scan of cell counts (1 block) ----------------
__global__ __launch_bounds__(NCELL) void scan_kernel() {
    __shared__ int wsum[NCELL / 32];
    int tid = threadIdx.x, lane = tid & 31, wid = tid >> 5;
    int v = g_cellcnt[tid];
    int x = v;
#pragma unroll
    for (int o = 1; o < 32; o <<= 1) {
        int y = __shfl_up_sync(0xffffffffu, x, o);
        if (lane >= o) x += y;
    }
    if (lane == 31) wsum[wid] = x;
    __syncthreads();
    if (wid == 0) {
        int s = (lane < NCELL / 32) ? wsum[lane] : 0;
#pragma unroll
        for (int o = 1; o < 32; o <<= 1) {
            int y = __shfl_up_sync(0xffffffffu, s, o);
            if (lane >= o) s += y;
        }
        if (lane < NCELL / 32) wsum[lane] = s;
    }
    __syncthreads();
    int pre = (wid > 0) ? wsum[wid - 1] : 0;
    g_cellcur[tid] = pre + x - v;
}
// ---------------- K0d: scatter into sorted order ----------------
__global__ void scatter_kernel() {
    int i = blockIdx.x * blockDim.x + threadIdx.x;
    if (i < NPTS) {
        float x = g_px[i], y = g_py[i], z = g_pz[i];
        int slot = atomicAdd(&g_cellcur[cell_of(x, y, z)], 1);
        g_sx[slot] = x; g_sy[slot] = y; g_sz[slot] = z;
        g_sidx[slot] = i;
    }
}
// ---------------- K0e: per-group bounding boxes (1 warp / group) ----------------
__global__ __launch_bounds__(256) void boxes_kernel() {
    const int lane = threadIdx.x & 31;
    const int g = blockIdx.x * 8 + (threadIdx.x >> 5);
    const int base = g * GSZ + 2 * lane;
    float2 x2 = *(const float2*)&g_sx[base];
    float2 y2 = *(const float2*)&g_sy[base];
    float2 z2 = *(const float2*)&g_sz[base];
    // positive coords: u32 bit order == float order
    unsigned mnx = __reduce_min_sync(0xffffffffu, min(__float_as_uint(x2.x), __float_as_uint(x2.y)));
    unsigned mxx = __reduce_max_sync(0xffffffffu, max(__float_as_uint(x2.x), __float_as_uint(x2.y)));
    unsigned mny = __reduce_min_sync(0xffffffffu, min(__float_as_uint(y2.x), __float_as_uint(y2.y)));
    unsigned mxy = __reduce_max_sync(0xffffffffu, max(__float_as_uint(y2.x), __float_as_uint(y2.y)));
    unsigned mnz = __reduce_min_sync(0xffffffffu, min(__float_as_uint(z2.x), __float_as_uint(z2.y)));
    unsigned mxz = __reduce_max_sync(0xffffffffu, max(__float_as_uint(z2.x), __float_as_uint(z2.y)));
    if (lane == 0) {
        g_boxa[g] = make_float4(__uint_as_float(mnx), __uint_as_float(mny),
                                __uint_as_float(mnz), 3.402823466e38f);
        g_boxb[g] = make_float4(__uint_as_float(mxx), __uint_as_float(mxy),
                                __uint_as_float(mxz), 0.0f);
    }
}

// ---------------- K1: FPS — ONE warp, barrier-free, box-pruned, tie-exact ------
// Per-point key = (min_d_bits<<32)|~orig_idx. Update = u64 min (pure float min
// semantics, idx rides along). Argmax over group keys = max d2, ties -> min
// ORIGINAL index == jnp.argmax. d2 = ((dx*dx+dy*dy)+dz*dz), RN ops, no FMA
// (bit-exact vs XLA). A group is skipped only when a conservative lower bound
// proves its update is a no-op. Each group caches its argmax point's coords
// (s_gwin) so the next center needs no global-memory round trip.
__global__ __launch_bounds__(32, 1) void fps_kernel() {
    extern __shared__ unsigned char smem_raw[];
    ull*    s_key  = (ull*)smem_raw;                 // [NPTS]   128KB
    ull*    s_gkey = s_key + NPTS;                   // [NGRP]   2KB
    float4* s_boxa = (float4*)(s_gkey + NGRP);       // [NGRP]   {min, gmax}
    float4* s_boxb = s_boxa + NGRP;                  // [NGRP]   {max, -}
    float4* s_gwin = s_boxb + NGRP;                  // [NGRP]   group winner xyz
    int*    s_act  = (int*)(s_gwin + NGRP);          // [NGRP]

    const int lane = threadIdx.x;

    // ---- init (one warp) ----
    for (int p = lane; p < NPTS; p += 32)
        s_key[p] = (0x7f7fffffULL << 32) | (unsigned)(~g_sidx[p]);
    for (int g = lane; g < NGRP; g += 32) {
        s_boxa[g] = g_boxa[g];
        s_boxb[g] = g_boxb[g];
        s_gkey[g] = 0;
        s_gwin[g] = make_float4(0.f, 0.f, 0.f, 0.f);
    }
    float cx = g_px[0], cy = g_py[0], cz = g_pz[0];
    if (lane == 0) { g_cx[0] = cx; g_cy[0] = cy; g_cz[0] = cz; }
    __syncwarp();

    for (int s = 0; s < NS - 1; s++) {
        // ---- prune: 8 boxes per lane, ballot-compacted active list ----
        int cnt = 0;
#pragma unroll
        for (int j = 0; j < 8; j++) {
            const int g = j * 32 + lane;
            float4 a = s_boxa[g];
            float4 b = s_boxb[g];
            float dx = fmaxf(fmaxf(a.x - cx, cx - b.x), 0.0f);
            float dy = fmaxf(fmaxf(a.y - cy, cy - b.y), 0.0f);
            float dz = fmaxf(fmaxf(a.z - cz, cz - b.z), 0.0f);
            float lb = dx * dx + dy * dy + dz * dz;
            bool act = (lb * 0.99999f - 1e-6f < a.w);
            unsigned bal = __ballot_sync(0xffffffffu, act);
            if (act) s_act[cnt + __popc(bal & ((1u << lane) - 1u))] = g;
            cnt += __popc(bal);
        }
        __syncwarp();

        // ---- update active groups (2 points / lane / group) ----
        const unsigned nbx = __float_as_uint(-cx);
        const unsigned nby = __float_as_uint(-cy);
        const unsigned nbz = __float_as_uint(-cz);
        const ull nlx = pack2(nbx, nbx);
        const ull nly = pack2(nby, nby);
        const ull nlz = pack2(nbz, nbz);
        for (int a = 0; a < cnt; a++) {
            const int g = s_act[a];
            const int base = g * GSZ + 2 * lane;
            ull X = __ldg((const ull*)&g_sx[base]);
            ull Y = __ldg((const ull*)&g_sy[base]);
            ull Z = __ldg((const ull*)&g_sz[base]);
            ull dx = f2_add(X, nlx);   // x - cx, exact RN
            ull dy = f2_add(Y, nly);
            ull dz = f2_add(Z, nlz);
            ull d2 = f2_add(f2_add(f2_mul(dx, dx), f2_mul(dy, dy)), f2_mul(dz, dz));
            unsigned d0, d1; unpack2(d0, d1, d2);
            ulonglong2 kp = *(ulonglong2*)&s_key[base];
            ull k0 = umin64(kp.x, ((ull)d0 << 32) | (unsigned)kp.x);
            ull k1 = umin64(kp.y, ((ull)d1 << 32) | (unsigned)kp.y);
            *(ulonglong2*)&s_key[base] = make_ulonglong2(k0, k1);
            // group argmax via hi/lo REDUX (exact u64-max semantics)
            ull m = umax64(k0, k1);
            unsigned hi = (unsigned)(m >> 32);
            unsigned gm = __reduce_max_sync(0xffffffffu, hi);
            unsigned lc = (hi == gm) ? (unsigned)m : 0u;
            unsigned gl = __reduce_max_sync(0xffffffffu, lc);
            if (hi == gm && (unsigned)m == gl) {          // unique winning lane
                bool first = ((unsigned)(k0 >> 32) == gm && (unsigned)k0 == gl);
                unsigned xl, xh, yl, yh, zl, zh;
                unpack2(xl, xh, X); unpack2(yl, yh, Y); unpack2(zl, zh, Z);
                s_gwin[g] = make_float4(__uint_as_float(first ? xl : xh),
                                        __uint_as_float(first ? yl : yh),
                                        __uint_as_float(first ? zl : zh), 0.f);
                s_gkey[g] = ((ull)gm << 32) | gl;
                s_boxa[g].w = __uint_as_float(gm);        // gmax for pruning
            }
        }
        __syncwarp();

        // ---- global argmax over 256 group keys ----
        ull best = 0;
#pragma unroll
        for (int j = 0; j < 8; j++) best = umax64(best, s_gkey[j * 32 + lane]);
        unsigned bh = (unsigned)(best >> 32);
        unsigned gm = __reduce_max_sync(0xffffffffu, bh);
        unsigned lc = (bh == gm) ? (unsigned)best : 0u;
        unsigned gl = __reduce_max_sync(0xffffffffu, lc);
        const ull wkey = ((ull)gm << 32) | gl;

        float wx = 0.f, wy = 0.f, wz = 0.f;
        bool have = (best == wkey);
        if (have) {
#pragma unroll
            for (int j = 0; j < 8; j++) {
                const int g = j * 32 + lane;
                if (s_gkey[g] == wkey) {
                    float4 w = s_gwin[g];
                    wx = w.x; wy = w.y; wz = w.z;
                }
            }
        }
        unsigned bal = __ballot_sync(0xffffffffu, have);
        int src = __ffs(bal) - 1;
        cx = __shfl_sync(0xffffffffu, wx, src);
        cy = __shfl_sync(0xffffffffu, wy, src);
        cz = __shfl_sync(0xffffffffu, wz, src);
        if (lane == src) { g_cx[s + 1] = wx; g_cy[s + 1] = wy; g_cz[s + 1] = wz; }
        __syncwarp();
    }
}

// ---------------- K2: top-10 nearest per center (1 warp / center) ----------------
__global__ __launch_bounds__(256) void topk_kernel() {
    const int lane = threadIdx.x & 31;
    const int w    = threadIdx.x >> 5;
    const int c    = blockIdx.x * 8 + w;
    const float cx = g_cx[c], cy = g_cy[c], cz = g_cz[c];

    ull heap[KNB];  // sorted ascending; key = (d2_bits<<32)|idx
#pragma unroll
    for (int q = 0; q < KNB; q++) heap[q] = ~0ULL;

#pragma unroll 4
    for (int i = 0; i < NPTS / 32; i++) {
        int p = lane + 32 * i;
        float dx = __fsub_rn(cx, __ldg(&g_px[p]));
        float dy = __fsub_rn(cy, __ldg(&g_py[p]));
        float dz = __fsub_rn(cz, __ldg(&g_pz[p]));
        float d2 = __fadd_rn(__fadd_rn(__fmul_rn(dx, dx), __fmul_rn(dy, dy)), __fmul_rn(dz, dz));
        ull key = ((ull)__float_as_uint(d2) << 32) | (unsigned)p;
        if (key < heap[KNB - 1]) {
            heap[KNB - 1] = key;
#pragma unroll
            for (int q = KNB - 1; q > 0; q--) {
                ull a = heap[q - 1], b = heap[q];
                heap[q - 1] = (a < b) ? a : b;
                heap[q]     = (a < b) ? b : a;
            }
        }
    }
#pragma unroll
    for (int r = 0; r < KNB; r++) {
        ull cur = heap[0];
        unsigned hi = (unsigned)(cur >> 32);
        unsigned mh = __reduce_min_sync(0xffffffffu, hi);
        unsigned lo = (hi == mh) ? (unsigned)cur : 0xffffffffu;
        unsigned ml = __reduce_min_sync(0xffffffffu, lo);
        if (hi == mh && (unsigned)cur == ml) {
#pragma unroll
            for (int q = 0; q < KNB - 1; q++) heap[q] = heap[q + 1];
            heap[KNB - 1] = ~0ULL;
        }
        if (lane == 0)
            g_src[c * KNB + r] = (__uint_as_float(mh) <= R2) ? (int)ml : -1;
    }
}

// ---------------- K3: MLP + masked segment max (CPB centers / block) ----------------
__global__ __launch_bounds__(128) void mlp_kernel(const float* __restrict__ W1,
                                                  const float* __restrict__ b1,
                                                  const float* __restrict__ W2,
                                                  const float* __restrict__ b2,
                                                  float* __restrict__ out) {
    const int c0 = blockIdx.x * CPB;
    const int t  = threadIdx.x;
    __shared__ float s_w2[64 * 128];
    __shared__ float s_hid[64];
    __shared__ int   s_src[CPB * KNB];

#pragma unroll
    for (int q = 0; q < 64; q++) s_w2[q * 128 + t] = W2[q * 128 + t];
    for (int i = t; i < CPB * KNB; i += 128) s_src[i] = g_src[c0 * KNB + i];

    float w1a = 0.f, w1b = 0.f, w1c = 0.f, bb1 = 0.f;
    if (t < 64) { w1a = W1[t]; w1b = W1[64 + t]; w1c = W1[128 + t]; bb1 = b1[t]; }
    const float b2c = b2[t];
    __syncthreads();

    for (int cc = 0; cc < CPB; cc++) {
        const int c = c0 + cc;
        const float bx = g_px[c], by = g_py[c], bz = g_pz[c];
        float acc = -3.402823466e38f;
        bool any = false;
        for (int nb = 0; nb < KNB; nb++) {
            int sp = s_src[cc * KNB + nb];
            if (sp >= 0) {
                any = true;
                if (t < 64) {
                    float rx = g_px[sp] - bx, ry = g_py[sp] - by, rz = g_pz[sp] - bz;
                    float h = bb1 + rx * w1a + ry * w1b + rz * w1c;
                    s_hid[t] = h > 0.f ? h : 0.f;
                }
                __syncthreads();
                float a = b2c;
#pragma unroll
                for (int k = 0; k < 64; k++) a = fmaf(s_hid[k], s_w2[k * 128 + t], a);
                acc = fmaxf(acc, a);
                __syncthreads();
            }
        }
        out[c * 128 + t] = any ? acc : 0.0f;
    }
}

// ---------------- K4: zero-fill rows NS..NPTS-1 ----------------
__global__ void fill_kernel(float* __restrict__ out) {
    int i = blockIdx.x * blockDim.x + threadIdx.x;
    if (i < (NPTS - NS) * 128) out[NS * 128 + i] = 0.0f;
}

// ---------------- launch ----------------
extern "C" void kernel_launch(void* const* d_in, const int* in_sizes, int n_in,
                              void* d_out, int out_size) {
    const float* pos = (const float*)d_in[0];
    const float* W1 = (const float*)d_in[2];
    const float* b1 = (const float*)d_in[3];
    const float* W2 = (const float*)d_in[4];
    const float* b2 = (const float*)d_in[5];
    float* out = (float*)d_out;

    prep_kernel<<<(NPTS + 255) / 256, 256>>>(pos);
    hist_kernel<<<(NPTS + 255) / 256, 256>>>();
    scan_kernel<<<1, NCELL>>>();
    scatter_kernel<<<(NPTS + 255) / 256, 256>>>();
    boxes_kernel<<<NGRP / 8, 256>>>();

    const int fps_smem = NPTS * 8        // s_key
                       + NGRP * 8        // s_gkey
                       + NGRP * 16 * 3   // s_boxa, s_boxb, s_gwin
                       + NGRP * 4;       // s_act
    cudaFuncSetAttribute(fps_kernel, cudaFuncAttributeMaxDynamicSharedMemorySize, fps_smem);
    fps_kernel<<<1, 32, fps_smem>>>();

    topk_kernel<<<NS / 8, 256>>>();

    mlp_kernel<<<NS / CPB, 128>>>(W1, b1, W2, b2, out);
    fill_kernel<<<((NPTS - NS) * 128 + 255) / 256, 256>>>(out);
}

// round 6
// speedup vs baseline: 1.5117x; 1.5117x over previous
#include <cuda_runtime.h>

#define NPTS 16384
#define NS   8192
#define KNB  10
#define R2   0.0625f
#define NGRP 256
#define GSZ  64
#define GDIM 8
#define NCELL (GDIM * GDIM * GDIM)
#define CPB  32
#define GPW  16           // groups per warp (16 warps x 16 = 256)

typedef unsigned long long ull;

// ---------------- global scratch (no allocation allowed) ----------------
__device__ __align__(16) float g_px[NPTS];   // original order SoA
__device__ __align__(16) float g_py[NPTS];
__device__ __align__(16) float g_pz[NPTS];
__device__ __align__(16) float g_sx[NPTS];   // spatially sorted SoA
__device__ __align__(16) float g_sy[NPTS];
__device__ __align__(16) float g_sz[NPTS];
__device__ __align__(16) int   g_sidx[NPTS]; // sorted slot -> original index
__device__ int g_cellcnt[NCELL];
__device__ int g_cellcur[NCELL];
__device__ float4 g_boxa[NGRP];              // {minx,miny,minz, FLT_MAX(gmax)}
__device__ float4 g_boxb[NGRP];              // {maxx,maxy,maxz, 0}
__device__ float g_cx[NS], g_cy[NS], g_cz[NS];
__device__ int   g_src[NS * KNB];

// ---------------- packed f32x2 helpers (bit-exact IEEE RN per lane) ------
__device__ __forceinline__ ull f2_add(ull a, ull b) {
    ull r; asm("add.rn.f32x2 %0, %1, %2;" : "=l"(r) : "l"(a), "l"(b)); return r;
}
__device__ __forceinline__ ull f2_mul(ull a, ull b) {
    ull r; asm("mul.rn.f32x2 %0, %1, %2;" : "=l"(r) : "l"(a), "l"(b)); return r;
}
__device__ __forceinline__ ull pack2(unsigned lo, unsigned hi) {
    ull r; asm("mov.b64 %0, {%1, %2};" : "=l"(r) : "r"(lo), "r"(hi)); return r;
}
__device__ __forceinline__ void unpack2(unsigned &lo, unsigned &hi, ull v) {
    asm("mov.b64 {%0, %1}, %2;" : "=r"(lo), "=r"(hi) : "l"(v));
}
__device__ __forceinline__ ull umax64(ull a, ull b) { return a > b ? a : b; }
__device__ __forceinline__ ull umin64(ull a, ull b) { return a < b ? a : b; }
__device__ __forceinline__ int cell_of(float x, float y, float z) {
    int cx = min(GDIM - 1, (int)(x * (float)GDIM));
    int cy = min(GDIM - 1, (int)(y * (float)GDIM));
    int cz = min(GDIM - 1, (int)(z * (float)GDIM));
    return (cz * GDIM + cy) * GDIM + cx;
}

// ---------------- K0: AoS -> SoA + zero counters ----------------
__global__ void prep_kernel(const float* __restrict__ pos) {
    int i = blockIdx.x * blockDim.x + threadIdx.x;
    if (i < NCELL) g_cellcnt[i] = 0;
    if (i < NPTS) {
        g_px[i] = pos[3 * i + 0];
        g_py[i] = pos[3 * i + 1];
        g_pz[i] = pos[3 * i + 2];
    }
}
// ---------------- K0b: histogram ----------------
__global__ void hist_kernel() {
    int i = blockIdx.x * blockDim.x + threadIdx.x;
    if (i < NPTS) atomicAdd(&g_cellcnt[cell_of(g_px[i], g_py[i], g_pz[i])], 1);
}
// ---------------- K0c: exclusive scan of cell counts (1 block) ----------------
__global__ __launch_bounds__(NCELL) void scan_kernel() {
    __shared__ int wsum[NCELL / 32];
    int tid = threadIdx.x, lane = tid & 31, wid = tid >> 5;
    int v = g_cellcnt[tid];
    int x = v;
#pragma unroll
    for (int o = 1; o < 32; o <<= 1) {
        int y = __shfl_up_sync(0xffffffffu, x, o);
        if (lane >= o) x += y;
    }
    if (lane == 31) wsum[wid] = x;
    __syncthreads();
    if (wid == 0) {
        int s = (lane < NCELL / 32) ? wsum[lane] : 0;
#pragma unroll
        for (int o = 1; o < 32; o <<= 1) {
            int y = __shfl_up_sync(0xffffffffu, s, o);
            if (lane >= o) s += y;
        }
        if (lane < NCELL / 32) wsum[lane] = s;
    }
    __syncthreads();
    int pre = (wid > 0) ? wsum[wid - 1] : 0;
    g_cellcur[tid] = pre + x - v;
}
// ---------------- K0d: scatter into sorted order ----------------
__global__ void scatter_kernel() {
    int i = blockIdx.x * blockDim.x + threadIdx.x;
    if (i < NPTS) {
        float x = g_px[i], y = g_py[i], z = g_pz[i];
        int slot = atomicAdd(&g_cellcur[cell_of(x, y, z)], 1);
        g_sx[slot] = x; g_sy[slot] = y; g_sz[slot] = z;
        g_sidx[slot] = i;
    }
}
// ---------------- K0e: per-group bounding boxes (1 warp / group) ----------------
__global__ __launch_bounds__(256) void boxes_kernel() {
    const int lane = threadIdx.x & 31;
    const int g = blockIdx.x * 8 + (threadIdx.x >> 5);
    const int base = g * GSZ + 2 * lane;
    float2 x2 = *(const float2*)&g_sx[base];
    float2 y2 = *(const float2*)&g_sy[base];
    float2 z2 = *(const float2*)&g_sz[base];
    unsigned mnx = __reduce_min_sync(0xffffffffu, min(__float_as_uint(x2.x), __float_as_uint(x2.y)));
    unsigned mxx = __reduce_max_sync(0xffffffffu, max(__float_as_uint(x2.x), __float_as_uint(x2.y)));
    unsigned mny = __reduce_min_sync(0xffffffffu, min(__float_as_uint(y2.x), __float_as_uint(y2.y)));
    unsigned mxy = __reduce_max_sync(0xffffffffu, max(__float_as_uint(y2.x), __float_as_uint(y2.y)));
    unsigned mnz = __reduce_min_sync(0xffffffffu, min(__float_as_uint(z2.x), __float_as_uint(z2.y)));
    unsigned mxz = __reduce_max_sync(0xffffffffu, max(__float_as_uint(z2.x), __float_as_uint(z2.y)));
    if (lane == 0) {
        g_boxa[g] = make_float4(__uint_as_float(mnx), __uint_as_float(mny),
                                __uint_as_float(mnz), 3.402823466e38f);
        g_boxb[g] = make_float4(__uint_as_float(mxx), __uint_as_float(mxy),
                                __uint_as_float(mxz), 0.0f);
    }
}

// ---------------- K1: FPS — 16 warps x 16 groups, keys in regs, 1 barrier/step -
// Warp w owns groups 16w..16w+15; each lane owns 2 points per group: keys live
// in REGISTERS, coords in SMEM. key = (min_d_bits<<32)|~orig_idx; u64 max =
// max d2, tie -> min original index == jnp.argmax. d2 = ((dx*dx+dy*dy)+dz*dz)
// with RN mul/add, no FMA (bit-exact vs XLA). Groups skipped only when a
// conservative bound proves the update is a no-op. Single __syncthreads per
// step with parity-double-buffered warp-best slots.
__global__ __launch_bounds__(512, 1) void fps_kernel() {
    extern __shared__ unsigned char smem_raw[];
    ull*    s_x2   = (ull*)smem_raw;               // [NPTS/2]  64KB
    ull*    s_y2   = s_x2 + NPTS / 2;              // 64KB
    ull*    s_z2   = s_y2 + NPTS / 2;              // 64KB
    ull*    s_gkey = s_z2 + NPTS / 2;              // [NGRP]
    float4* s_boxa = (float4*)(s_gkey + NGRP);     // [NGRP] {min xyz, gmax}
    float4* s_boxb = s_boxa + NGRP;                // [NGRP]
    float4* s_gwin = s_boxb + NGRP;                // [NGRP] group argmax coords
    ull*    s_wkey = (ull*)(s_gwin + NGRP);        // [2][16]
    float4* s_wxyz = (float4*)(s_wkey + 32);       // [2][16]

    const int tid  = threadIdx.x;
    const int lane = tid & 31;
    const int w    = tid >> 5;

    // ---- stage coords into smem; keys into registers ----
    for (int i = tid; i < NPTS / 2; i += 512) {
        s_x2[i] = ((const ull*)g_sx)[i];
        s_y2[i] = ((const ull*)g_sy)[i];
        s_z2[i] = ((const ull*)g_sz)[i];
    }
    ull K0[GPW], K1[GPW];
#pragma unroll
    for (int j = 0; j < GPW; j++) {
        const int p = (w * GPW + j) * GSZ + 2 * lane;
        int2 si = *(const int2*)&g_sidx[p];
        K0[j] = (0x7f7fffffULL << 32) | (unsigned)(~si.x);
        K1[j] = (0x7f7fffffULL << 32) | (unsigned)(~si.y);
    }
    if (tid < NGRP) {
        s_boxa[tid] = g_boxa[tid];        // .w = FLT_MAX (gmax)
        s_boxb[tid] = g_boxb[tid];
        s_gkey[tid] = 0;
        s_gwin[tid] = make_float4(0.f, 0.f, 0.f, 0.f);
    }
    float cx = g_px[0], cy = g_py[0], cz = g_pz[0];
    if (tid == 0) { g_cx[0] = cx; g_cy[0] = cy; g_cz[0] = cz; }
    __syncthreads();

    int par = 0;
    for (int s = 0; s < NS - 1; s++) {
        // ---- prune: lane j (<16) tests box of group 16w+j ----
        bool act = false;
        if (lane < GPW) {
            const int g = w * GPW + lane;
            float4 a = s_boxa[g];
            float4 b = s_boxb[g];
            float dx = fmaxf(fmaxf(a.x - cx, cx - b.x), 0.0f);
            float dy = fmaxf(fmaxf(a.y - cy, cy - b.y), 0.0f);
            float dz = fmaxf(fmaxf(a.z - cz, cz - b.z), 0.0f);
            float lb = dx * dx + dy * dy + dz * dz;
            act = (lb * 0.99999f - 1e-6f < a.w);
        }
        const unsigned amask = __ballot_sync(0xffffffffu, act);

        // ---- update active groups (keys in regs, coords via LDS) ----
        const unsigned nbx = __float_as_uint(-cx);
        const unsigned nby = __float_as_uint(-cy);
        const unsigned nbz = __float_as_uint(-cz);
        const ull nlx = pack2(nbx, nbx);
        const ull nly = pack2(nby, nby);
        const ull nlz = pack2(nbz, nbz);
#pragma unroll
        for (int j = 0; j < GPW; j++) {
            if ((amask >> j) & 1u) {              // warp-uniform branch
                const int pp = (w * GPW + j) * 32 + lane;   // point-pair index
                const ull X = s_x2[pp];
                const ull Y = s_y2[pp];
                const ull Z = s_z2[pp];
                ull dx = f2_add(X, nlx);          // x - cx, exact RN
                ull dy = f2_add(Y, nly);
                ull dz = f2_add(Z, nlz);
                ull d2 = f2_add(f2_add(f2_mul(dx, dx), f2_mul(dy, dy)), f2_mul(dz, dz));
                unsigned d0, d1; unpack2(d0, d1, d2);
                K0[j] = umin64(K0[j], ((ull)d0 << 32) | (unsigned)K0[j]);
                K1[j] = umin64(K1[j], ((ull)d1 << 32) | (unsigned)K1[j]);
                ull m = umax64(K0[j], K1[j]);
                unsigned hi = (unsigned)(m >> 32);
                unsigned gm = __reduce_max_sync(0xffffffffu, hi);
                unsigned cand = __ballot_sync(0xffffffffu, hi == gm);
                bool win;
                if (__popc(cand) == 1) {          // unique hi winner (common)
                    win = (hi == gm);
                } else {                          // exact u64 tie-break on lo
                    unsigned lc = (hi == gm) ? (unsigned)m : 0u;
                    unsigned gl = __reduce_max_sync(0xffffffffu, lc);
                    unsigned wb = __ballot_sync(0xffffffffu, hi == gm && (unsigned)m == gl);
                    win = (lane == (__ffs(wb) - 1));
                }
                if (win) {                        // group argmax owner
                    const int g = w * GPW + j;
                    const bool first = (m == K0[j]);
                    unsigned xl, xh, yl, yh, zl, zh;
                    unpack2(xl, xh, X); unpack2(yl, yh, Y); unpack2(zl, zh, Z);
                    s_gwin[g] = make_float4(__uint_as_float(first ? xl : xh),
                                            __uint_as_float(first ? yl : yh),
                                            __uint_as_float(first ? zl : zh), 0.f);
                    s_gkey[g] = m;
                    s_boxa[g].w = __uint_as_float(gm);    // refresh gmax
                }
            }
        }
        __syncwarp();

        // ---- warp best over its 16 groups ----
        ull kj = 0; float4 winc = make_float4(0.f, 0.f, 0.f, 0.f);
        if (lane < GPW) {
            const int g = w * GPW + lane;
            kj = s_gkey[g];
            winc = s_gwin[g];
        }
        {
            unsigned hi = (unsigned)(kj >> 32);
            unsigned gm = __reduce_max_sync(0xffffffffu, hi);
            unsigned lc = (hi == gm) ? (unsigned)kj : 0u;
            unsigned gl = __reduce_max_sync(0xffffffffu, lc);
            unsigned wb = __ballot_sync(0xffffffffu, hi == gm && (unsigned)kj == gl);
            if (lane == (__ffs(wb) - 1)) {        // unique winner lane
                s_wkey[par * 16 + w] = kj;
                s_wxyz[par * 16 + w] = winc;
            }
        }
        __syncthreads();                          // the ONE barrier

        // ---- global best over 16 warp entries (computed by every warp) ----
        ull kw = (lane < 16) ? s_wkey[par * 16 + lane] : 0ULL;
        unsigned hi = (unsigned)(kw >> 32);
        unsigned gm = __reduce_max_sync(0xffffffffu, hi);
        unsigned lc = (hi == gm) ? (unsigned)kw : 0u;
        unsigned gl = __reduce_max_sync(0xffffffffu, lc);
        unsigned bal = __ballot_sync(0xffffffffu, hi == gm && (unsigned)kw == gl);
        const int L = __ffs(bal) - 1;             // winning warp slot
        float4 c4 = s_wxyz[par * 16 + L];         // uniform LDS broadcast
        cx = c4.x; cy = c4.y; cz = c4.z;
        if (tid == 0) { g_cx[s + 1] = cx; g_cy[s + 1] = cy; g_cz[s + 1] = cz; }
        par ^= 1;                                 // next step: other buffer
    }
}

// ---------------- K2: top-10 nearest per center (1 warp / center) ----------------
__global__ __launch_bounds__(256) void topk_kernel() {
    const int lane = threadIdx.x & 31;
    const int w    = threadIdx.x >> 5;
    const int c    = blockIdx.x * 8 + w;
    const float cx = g_cx[c], cy = g_cy[c], cz = g_cz[c];

    ull heap[KNB];  // sorted ascending; key = (d2_bits<<32)|idx
#pragma unroll
    for (int q = 0; q < KNB; q++) heap[q] = ~0ULL;

#pragma unroll 4
    for (int i = 0; i < NPTS / 32; i++) {
        int p = lane + 32 * i;
        float dx = __fsub_rn(cx, __ldg(&g_px[p]));
        float dy = __fsub_rn(cy, __ldg(&g_py[p]));
        float dz = __fsub_rn(cz, __ldg(&g_pz[p]));
        float d2 = __fadd_rn(__fadd_rn(__fmul_rn(dx, dx), __fmul_rn(dy, dy)), __fmul_rn(dz, dz));
        ull key = ((ull)__float_as_uint(d2) << 32) | (unsigned)p;
        if (key < heap[KNB - 1]) {
            heap[KNB - 1] = key;
#pragma unroll
            for (int q = KNB - 1; q > 0; q--) {
                ull a = heap[q - 1], b = heap[q];
                heap[q - 1] = (a < b) ? a : b;
                heap[q]     = (a < b) ? b : a;
            }
        }
    }
#pragma unroll
    for (int r = 0; r < KNB; r++) {
        ull cur = heap[0];
        unsigned hi = (unsigned)(cur >> 32);
        unsigned mh = __reduce_min_sync(0xffffffffu, hi);
        unsigned lo = (hi == mh) ? (unsigned)cur : 0xffffffffu;
        unsigned ml = __reduce_min_sync(0xffffffffu, lo);
        if (hi == mh && (unsigned)cur == ml) {
#pragma unroll
            for (int q = 0; q < KNB - 1; q++) heap[q] = heap[q + 1];
            heap[KNB - 1] = ~0ULL;
        }
        if (lane == 0)
            g_src[c * KNB + r] = (__uint_as_float(mh) <= R2) ? (int)ml : -1;
    }
}

// ---------------- K3: MLP + masked segment max (CPB centers / block) ----------------
__global__ __launch_bounds__(128) void mlp_kernel(const float* __restrict__ W1,
                                                  const float* __restrict__ b1,
                                                  const float* __restrict__ W2,
                                                  const float* __restrict__ b2,
                                                  float* __restrict__ out) {
    const int c0 = blockIdx.x * CPB;
    const int t  = threadIdx.x;
    __shared__ float s_w2[64 * 128];
    __shared__ float s_hid[64];
    __shared__ int   s_src[CPB * KNB];

#pragma unroll
    for (int q = 0; q < 64; q++) s_w2[q * 128 + t] = W2[q * 128 + t];
    for (int i = t; i < CPB * KNB; i += 128) s_src[i] = g_src[c0 * KNB + i];

    float w1a = 0.f, w1b = 0.f, w1c = 0.f, bb1 = 0.f;
    if (t < 64) { w1a = W1[t]; w1b = W1[64 + t]; w1c = W1[128 + t]; bb1 = b1[t]; }
    const float b2c = b2[t];
    __syncthreads();

    for (int cc = 0; cc < CPB; cc++) {
        const int c = c0 + cc;
        const float bx = g_px[c], by = g_py[c], bz = g_pz[c];
        float acc = -3.402823466e38f;
        bool any = false;
        for (int nb = 0; nb < KNB; nb++) {
            int sp = s_src[cc * KNB + nb];
            if (sp >= 0) {
                any = true;
                if (t < 64) {
                    float rx = g_px[sp] - bx, ry = g_py[sp] - by, rz = g_pz[sp] - bz;
                    float h = bb1 + rx * w1a + ry * w1b + rz * w1c;
                    s_hid[t] = h > 0.f ? h : 0.f;
                }
                __syncthreads();
                float a = b2c;
#pragma unroll
                for (int k = 0; k < 64; k++) a = fmaf(s_hid[k], s_w2[k * 128 + t], a);
                acc = fmaxf(acc, a);
                __syncthreads();
            }
        }
        out[c * 128 + t] = any ? acc : 0.0f;
    }
}

// ---------------- K4: zero-fill rows NS..NPTS-1 ----------------
__global__ void fill_kernel(float* __restrict__ out) {
    int i = blockIdx.x * blockDim.x + threadIdx.x;
    if (i < (NPTS - NS) * 128) out[NS * 128 + i] = 0.0f;
}

// ---------------- launch ----------------
extern "C" void kernel_launch(void* const* d_in, const int* in_sizes, int n_in,
                              void* d_out, int out_size) {
    const float* pos = (const float*)d_in[0];
    const float* W1 = (const float*)d_in[2];
    const float* b1 = (const float*)d_in[3];
    const float* W2 = (const float*)d_in[4];
    const float* b2 = (const float*)d_in[5];
    float* out = (float*)d_out;

    prep_kernel<<<(NPTS + 255) / 256, 256>>>(pos);
    hist_kernel<<<(NPTS + 255) / 256, 256>>>();
    scan_kernel<<<1, NCELL>>>();
    scatter_kernel<<<(NPTS + 255) / 256, 256>>>();
    boxes_kernel<<<NGRP / 8, 256>>>();

    const int fps_smem = 3 * (NPTS / 2) * 8        // coords
                       + NGRP * 8                  // s_gkey
                       + NGRP * 16 * 3             // s_boxa, s_boxb, s_gwin
                       + 32 * 8 + 32 * 16;         // s_wkey, s_wxyz
    cudaFuncSetAttribute(fps_kernel, cudaFuncAttributeMaxDynamicSharedMemorySize, fps_smem);
    fps_kernel<<<1, 512, fps_smem>>>();

    topk_kernel<<<NS / 8, 256>>>();

    mlp_kernel<<<NS / CPB, 128>>>(W1, b1, W2, b2, out);
    fill_kernel<<<((NPTS - NS) * 128 + 255) / 256, 256>>>(out);
}

// round 7
// speedup vs baseline: 3.0872x; 2.0422x over previous
#include <cuda_runtime.h>

#define NPTS 16384
#define NS   8192
#define KNB  10
#define R2   0.0625f
#define NGRP 256
#define GSZ  64
#define GDIM 8
#define NCELL (GDIM * GDIM * GDIM)
#define CPB  32
#define GPW  16           // groups per warp (16 warps x 16 = 256)
#define NW   16           // warps

typedef unsigned long long ull;

// ---------------- global scratch (no allocation allowed) ----------------
__device__ __align__(16) float g_px[NPTS];   // original order SoA
__device__ __align__(16) float g_py[NPTS];
__device__ __align__(16) float g_pz[NPTS];
__device__ __align__(16) float g_sx[NPTS];   // spatially sorted SoA
__device__ __align__(16) float g_sy[NPTS];
__device__ __align__(16) float g_sz[NPTS];
__device__ __align__(16) int   g_sidx[NPTS]; // sorted slot -> original index
__device__ int g_cellcnt[NCELL];
__device__ int g_cellcur[NCELL];
__device__ float4 g_boxa[NGRP];              // {minx,miny,minz, FLT_MAX(gmax)}
__device__ float4 g_boxb[NGRP];              // {maxx,maxy,maxz, 0}
__device__ float g_cx[NS], g_cy[NS], g_cz[NS];
__device__ int   g_src[NS * KNB];

// ---------------- packed f32x2 helpers (bit-exact IEEE RN per lane) ------
__device__ __forceinline__ ull f2_add(ull a, ull b) {
    ull r; asm("add.rn.f32x2 %0, %1, %2;" : "=l"(r) : "l"(a), "l"(b)); return r;
}
__device__ __forceinline__ ull f2_mul(ull a, ull b) {
    ull r; asm("mul.rn.f32x2 %0, %1, %2;" : "=l"(r) : "l"(a), "l"(b)); return r;
}
__device__ __forceinline__ ull pack2(unsigned lo, unsigned hi) {
    ull r; asm("mov.b64 %0, {%1, %2};" : "=l"(r) : "r"(lo), "r"(hi)); return r;
}
__device__ __forceinline__ void unpack2(unsigned &lo, unsigned &hi, ull v) {
    asm("mov.b64 {%0, %1}, %2;" : "=r"(lo), "=r"(hi) : "l"(v));
}
__device__ __forceinline__ ull umax64(ull a, ull b) { return a > b ? a : b; }
__device__ __forceinline__ ull umin64(ull a, ull b) { return a < b ? a : b; }
__device__ __forceinline__ int cell_of(float x, float y, float z) {
    int cx = min(GDIM - 1, (int)(x * (float)GDIM));
    int cy = min(GDIM - 1, (int)(y * (float)GDIM));
    int cz = min(GDIM - 1, (int)(z * (float)GDIM));
    return (cz * GDIM + cy) * GDIM + cx;
}

// ---------------- K0: AoS -> SoA + zero counters ----------------
__global__ void prep_kernel(const float* __restrict__ pos) {
    int i = blockIdx.x * blockDim.x + threadIdx.x;
    if (i < NCELL) g_cellcnt[i] = 0;
    if (i < NPTS) {
        g_px[i] = pos[3 * i + 0];
        g_py[i] = pos[3 * i + 1];
        g_pz[i] = pos[3 * i + 2];
    }
}
// ---------------- K0b: histogram ----------------
__global__ void hist_kernel() {
    int i = blockIdx.x * blockDim.x + threadIdx.x;
    if (i < NPTS) atomicAdd(&g_cellcnt[cell_of(g_px[i], g_py[i], g_pz[i])], 1);
}
// ---------------- K0c: exclusive scan of cell counts (1 block) ----------------
__global__ __launch_bounds__(NCELL) void scan_kernel() {
    __shared__ int wsum[NCELL / 32];
    int tid = threadIdx.x, lane = tid & 31, wid = tid >> 5;
    int v = g_cellcnt[tid];
    int x = v;
#pragma unroll
    for (int o = 1; o < 32; o <<= 1) {
        int y = __shfl_up_sync(0xffffffffu, x, o);
        if (lane >= o) x += y;
    }
    if (lane == 31) wsum[wid] = x;
    __syncthreads();
    if (wid == 0) {
        int s = (lane < NCELL / 32) ? wsum[lane] : 0;
#pragma unroll
        for (int o = 1; o < 32; o <<= 1) {
            int y = __shfl_up_sync(0xffffffffu, s, o);
            if (lane >= o) s += y;
        }
        if (lane < NCELL / 32) wsum[lane] = s;
    }
    __syncthreads();
    int pre = (wid > 0) ? wsum[wid - 1] : 0;
    g_cellcur[tid] = pre + x - v;
}
// ---------------- K0d: scatter into sorted order ----------------
__global__ void scatter_kernel() {
    int i = blockIdx.x * blockDim.x + threadIdx.x;
    if (i < NPTS) {
        float x = g_px[i], y = g_py[i], z = g_pz[i];
        int slot = atomicAdd(&g_cellcur[cell_of(x, y, z)], 1);
        g_sx[slot] = x; g_sy[slot] = y; g_sz[slot] = z;
        g_sidx[slot] = i;
    }
}
// ---------------- K0e: per-group bounding boxes (1 warp / group) ----------------
__global__ __launch_bounds__(256) void boxes_kernel() {
    const int lane = threadIdx.x & 31;
    const int g = blockIdx.x * 8 + (threadIdx.x >> 5);
    const int base = g * GSZ + 2 * lane;
    float2 x2 = *(const float2*)&g_sx[base];
    float2 y2 = *(const float2*)&g_sy[base];
    float2 z2 = *(const float2*)&g_sz[base];
    unsigned mnx = __reduce_min_sync(0xffffffffu, min(__float_as_uint(x2.x), __float_as_uint(x2.y)));
    unsigned mxx = __reduce_max_sync(0xffffffffu, max(__float_as_uint(x2.x), __float_as_uint(x2.y)));
    unsigned mny = __reduce_min_sync(0xffffffffu, min(__float_as_uint(y2.x), __float_as_uint(y2.y)));
    unsigned mxy = __reduce_max_sync(0xffffffffu, max(__float_as_uint(y2.x), __float_as_uint(y2.y)));
    unsigned mnz = __reduce_min_sync(0xffffffffu, min(__float_as_uint(z2.x), __float_as_uint(z2.y)));
    unsigned mxz = __reduce_max_sync(0xffffffffu, max(__float_as_uint(z2.x), __float_as_uint(z2.y)));
    if (lane == 0) {
        g_boxa[g] = make_float4(__uint_as_float(mnx), __uint_as_float(mny),
                                __uint_as_float(mnz), 3.402823466e38f);
        g_boxb[g] = make_float4(__uint_as_float(mxx), __uint_as_float(mxy),
                                __uint_as_float(mxz), 0.0f);
    }
}

// ---------------- K1: FPS — interleaved group ownership, keys in regs ----------
// Warp w owns groups {j*16 + w, j=0..15} (INTERLEAVED): spatial runs of active
// groups spread across warps -> balanced update work under one barrier/step.
// Boxes/gkey/gwin stored owner-local (phys = w*16+j) -> conflict-free LDS.
// key = (min_d_bits<<32)|~orig_idx; u64 max = max d2, tie -> min original
// index == jnp.argmax. d2 = ((dx*dx+dy*dy)+dz*dz) with RN mul/add, no FMA
// (bit-exact vs XLA). Groups skipped only when a conservative bound proves the
// update is a no-op. Single __syncthreads/step, parity-double-buffered handoff.
__global__ __launch_bounds__(512, 1) void fps_kernel() {
    extern __shared__ unsigned char smem_raw[];
    ull*    s_x2   = (ull*)smem_raw;               // [NPTS/2]  64KB
    ull*    s_y2   = s_x2 + NPTS / 2;              // 64KB
    ull*    s_z2   = s_y2 + NPTS / 2;              // 64KB
    ull*    s_gkey = s_z2 + NPTS / 2;              // [NGRP] owner-local
    float4* s_boxa = (float4*)(s_gkey + NGRP);     // [NGRP] owner-local {min,gmax}
    float4* s_boxb = s_boxa + NGRP;                // [NGRP] owner-local
    float4* s_gwin = s_boxb + NGRP;                // [NGRP] owner-local argmax pt
    ull*    s_wkey = (ull*)(s_gwin + NGRP);        // [2][16]
    float4* s_wxyz = (float4*)(s_wkey + 32);       // [2][16]

    const int tid  = threadIdx.x;
    const int lane = tid & 31;
    const int w    = tid >> 5;

    // ---- stage coords into smem; keys into registers ----
    for (int i = tid; i < NPTS / 2; i += 512) {
        s_x2[i] = ((const ull*)g_sx)[i];
        s_y2[i] = ((const ull*)g_sy)[i];
        s_z2[i] = ((const ull*)g_sz)[i];
    }
    ull K0[GPW], K1[GPW];
#pragma unroll
    for (int j = 0; j < GPW; j++) {
        const int g = j * NW + w;                  // logical group (interleaved)
        const int p = g * GSZ + 2 * lane;
        int2 si = *(const int2*)&g_sidx[p];
        K0[j] = (0x7f7fffffULL << 32) | (unsigned)(~si.x);
        K1[j] = (0x7f7fffffULL << 32) | (unsigned)(~si.y);
    }
    if (tid < NGRP) {
        // phys tid = w0*16 + j0  <->  logical group j0*16 + w0
        const int gl = (tid & (GPW - 1)) * NW + (tid >> 4);
        s_boxa[tid] = g_boxa[gl];                  // .w = FLT_MAX (gmax)
        s_boxb[tid] = g_boxb[gl];
        s_gkey[tid] = 0;
        s_gwin[tid] = make_float4(0.f, 0.f, 0.f, 0.f);
    }
    float cx = g_px[0], cy = g_py[0], cz = g_pz[0];
    if (tid == 0) { g_cx[0] = cx; g_cy[0] = cy; g_cz[0] = cz; }
    __syncthreads();

    int par = 0;
    for (int s = 0; s < NS - 1; s++) {
        // ---- prune: lane j (<16) tests box phys w*16+j ----
        bool act = false;
        if (lane < GPW) {
            const int ph = w * GPW + lane;
            float4 a = s_boxa[ph];
            float4 b = s_boxb[ph];
            float dx = fmaxf(fmaxf(a.x - cx, cx - b.x), 0.0f);
            float dy = fmaxf(fmaxf(a.y - cy, cy - b.y), 0.0f);
            float dz = fmaxf(fmaxf(a.z - cz, cz - b.z), 0.0f);
            float lb = dx * dx + dy * dy + dz * dz;
            act = (lb * 0.99999f - 1e-6f < a.w);
        }
        const unsigned amask = __ballot_sync(0xffffffffu, act);

        // ---- update active groups (keys in regs, coords via LDS) ----
        const unsigned nbx = __float_as_uint(-cx);
        const unsigned nby = __float_as_uint(-cy);
        const unsigned nbz = __float_as_uint(-cz);
        const ull nlx = pack2(nbx, nbx);
        const ull nly = pack2(nby, nby);
        const ull nlz = pack2(nbz, nbz);
#pragma unroll
        for (int j = 0; j < GPW; j++) {
            if ((amask >> j) & 1u) {               // warp-uniform branch
                const int pp = (j * NW + w) * 32 + lane;   // point-pair index
                const ull X = s_x2[pp];
                const ull Y = s_y2[pp];
                const ull Z = s_z2[pp];
                ull dx = f2_add(X, nlx);           // x - cx, exact RN
                ull dy = f2_add(Y, nly);
                ull dz = f2_add(Z, nlz);
                ull d2 = f2_add(f2_add(f2_mul(dx, dx), f2_mul(dy, dy)), f2_mul(dz, dz));
                unsigned d0, d1; unpack2(d0, d1, d2);
                K0[j] = umin64(K0[j], ((ull)d0 << 32) | (unsigned)K0[j]);
                K1[j] = umin64(K1[j], ((ull)d1 << 32) | (unsigned)K1[j]);
                ull m = umax64(K0[j], K1[j]);
                unsigned hi = (unsigned)(m >> 32);
                unsigned gm = __reduce_max_sync(0xffffffffu, hi);
                unsigned cand = __ballot_sync(0xffffffffu, hi == gm);
                bool win;
                if (__popc(cand) == 1) {           // unique hi winner (common)
                    win = (hi == gm);
                } else {                           // exact u64 tie-break on lo
                    unsigned lc = (hi == gm) ? (unsigned)m : 0u;
                    unsigned gl = __reduce_max_sync(0xffffffffu, lc);
                    unsigned wb = __ballot_sync(0xffffffffu, hi == gm && (unsigned)m == gl);
                    win = (lane == (__ffs(wb) - 1));
                }
                if (win) {                         // group argmax owner
                    const int ph = w * GPW + j;    // owner-local slot
                    const bool first = (m == K0[j]);
                    unsigned xl, xh, yl, yh, zl, zh;
                    unpack2(xl, xh, X); unpack2(yl, yh, Y); unpack2(zl, zh, Z);
                    s_gwin[ph] = make_float4(__uint_as_float(first ? xl : xh),
                                             __uint_as_float(first ? yl : yh),
                                             __uint_as_float(first ? zl : zh), 0.f);
                    s_gkey[ph] = m;
                    s_boxa[ph].w = __uint_as_float(gm);   // refresh gmax
                }
            }
        }
        __syncwarp();

        // ---- warp best over its 16 groups (owner-local, conflict-free) ----
        ull kj = 0; float4 winc = make_float4(0.f, 0.f, 0.f, 0.f);
        if (lane < GPW) {
            const int ph = w * GPW + lane;
            kj = s_gkey[ph];
            winc = s_gwin[ph];
        }
        {
            unsigned hi = (unsigned)(kj >> 32);
            unsigned gm = __reduce_max_sync(0xffffffffu, hi);
            unsigned lc = (hi == gm) ? (unsigned)kj : 0u;
            unsigned gl = __reduce_max_sync(0xffffffffu, lc);
            unsigned wb = __ballot_sync(0xffffffffu, hi == gm && (unsigned)kj == gl);
            if (lane == (__ffs(wb) - 1)) {         // unique winner lane
                s_wkey[par * 16 + w] = kj;
                s_wxyz[par * 16 + w] = winc;
            }
        }
        __syncthreads();                           // the ONE barrier

        // ---- global best over 16 warp entries (computed by every warp) ----
        ull kw = (lane < 16) ? s_wkey[par * 16 + lane] : 0ULL;
        unsigned hi = (unsigned)(kw >> 32);
        unsigned gm = __reduce_max_sync(0xffffffffu, hi);
        unsigned lc = (hi == gm) ? (unsigned)kw : 0u;
        unsigned gl = __reduce_max_sync(0xffffffffu, lc);
        unsigned bal = __ballot_sync(0xffffffffu, hi == gm && (unsigned)kw == gl);
        const int L = __ffs(bal) - 1;              // winning warp slot
        float4 c4 = s_wxyz[par * 16 + L];          // uniform LDS broadcast
        cx = c4.x; cy = c4.y; cz = c4.z;
        if (tid == 0) { g_cx[s + 1] = cx; g_cy[s + 1] = cy; g_cz[s + 1] = cz; }
        par ^= 1;                                  // next step: other buffer
    }
}

// ---------------- K2: top-10 nearest per center (1 warp / center) ----------------
__global__ __launch_bounds__(256) void topk_kernel() {
    const int lane = threadIdx.x & 31;
    const int w    = threadIdx.x >> 5;
    const int c    = blockIdx.x * 8 + w;
    const float cx = g_cx[c], cy = g_cy[c], cz = g_cz[c];

    ull heap[KNB];  // sorted ascending; key = (d2_bits<<32)|idx
#pragma unroll
    for (int q = 0; q < KNB; q++) heap[q] = ~0ULL;

#pragma unroll 4
    for (int i = 0; i < NPTS / 32; i++) {
        int p = lane + 32 * i;
        float dx = __fsub_rn(cx, __ldg(&g_px[p]));
        float dy = __fsub_rn(cy, __ldg(&g_py[p]));
        float dz = __fsub_rn(cz, __ldg(&g_pz[p]));
        float d2 = __fadd_rn(__fadd_rn(__fmul_rn(dx, dx), __fmul_rn(dy, dy)), __fmul_rn(dz, dz));
        ull key = ((ull)__float_as_uint(d2) << 32) | (unsigned)p;
        if (key < heap[KNB - 1]) {
            heap[KNB - 1] = key;
#pragma unroll
            for (int q = KNB - 1; q > 0; q--) {
                ull a = heap[q - 1], b = heap[q];
                heap[q - 1] = (a < b) ? a : b;
                heap[q]     = (a < b) ? b : a;
            }
        }
    }
#pragma unroll
    for (int r = 0; r < KNB; r++) {
        ull cur = heap[0];
        unsigned hi = (unsigned)(cur >> 32);
        unsigned mh = __reduce_min_sync(0xffffffffu, hi);
        unsigned lo = (hi == mh) ? (unsigned)cur : 0xffffffffu;
        unsigned ml = __reduce_min_sync(0xffffffffu, lo);
        if (hi == mh && (unsigned)cur == ml) {
#pragma unroll
            for (int q = 0; q < KNB - 1; q++) heap[q] = heap[q + 1];
            heap[KNB - 1] = ~0ULL;
        }
        if (lane == 0)
            g_src[c * KNB + r] = (__uint_as_float(mh) <= R2) ? (int)ml : -1;
    }
}

// ---------------- K3: MLP + masked segment max (CPB centers / block) ----------------
__global__ __launch_bounds__(128) void mlp_kernel(const float* __restrict__ W1,
                                                  const float* __restrict__ b1,
                                                  const float* __restrict__ W2,
                                                  const float* __restrict__ b2,
                                                  float* __restrict__ out) {
    const int c0 = blockIdx.x * CPB;
    const int t  = threadIdx.x;
    __shared__ float s_w2[64 * 128];
    __shared__ float s_hid[64];
    __shared__ int   s_src[CPB * KNB];

#pragma unroll
    for (int q = 0; q < 64; q++) s_w2[q * 128 + t] = W2[q * 128 + t];
    for (int i = t; i < CPB * KNB; i += 128) s_src[i] = g_src[c0 * KNB + i];

    float w1a = 0.f, w1b = 0.f, w1c = 0.f, bb1 = 0.f;
    if (t < 64) { w1a = W1[t]; w1b = W1[64 + t]; w1c = W1[128 + t]; bb1 = b1[t]; }
    const float b2c = b2[t];
    __syncthreads();

    for (int cc = 0; cc < CPB; cc++) {
        const int c = c0 + cc;
        const float bx = g_px[c], by = g_py[c], bz = g_pz[c];
        float acc = -3.402823466e38f;
        bool any = false;
        for (int nb = 0; nb < KNB; nb++) {
            int sp = s_src[cc * KNB + nb];
            if (sp >= 0) {
                any = true;
                if (t < 64) {
                    float rx = g_px[sp] - bx, ry = g_py[sp] - by, rz = g_pz[sp] - bz;
                    float h = bb1 + rx * w1a + ry * w1b + rz * w1c;
                    s_hid[t] = h > 0.f ? h : 0.f;
                }
                __syncthreads();
                float a = b2c;
#pragma unroll
                for (int k = 0; k < 64; k++) a = fmaf(s_hid[k], s_w2[k * 128 + t], a);
                acc = fmaxf(acc, a);
                __syncthreads();
            }
        }
        out[c * 128 + t] = any ? acc : 0.0f;
    }
}

// ---------------- K4: zero-fill rows NS..NPTS-1 ----------------
__global__ void fill_kernel(float* __restrict__ out) {
    int i = blockIdx.x * blockDim.x + threadIdx.x;
    if (i < (NPTS - NS) * 128) out[NS * 128 + i] = 0.0f;
}

// ---------------- launch ----------------
extern "C" void kernel_launch(void* const* d_in, const int* in_sizes, int n_in,
                              void* d_out, int out_size) {
    const float* pos = (const float*)d_in[0];
    const float* W1 = (const float*)d_in[2];
    const float* b1 = (const float*)d_in[3];
    const float* W2 = (const float*)d_in[4];
    const float* b2 = (const float*)d_in[5];
    float* out = (float*)d_out;

    prep_kernel<<<(NPTS + 255) / 256, 256>>>(pos);
    hist_kernel<<<(NPTS + 255) / 256, 256>>>();
    scan_kernel<<<1, NCELL>>>();
    scatter_kernel<<<(NPTS + 255) / 256, 256>>>();
    boxes_kernel<<<NGRP / 8, 256>>>();

    const int fps_smem = 3 * (NPTS / 2) * 8        // coords
                       + NGRP * 8                  // s_gkey
                       + NGRP * 16 * 3             // s_boxa, s_boxb, s_gwin
                       + 32 * 8 + 32 * 16;         // s_wkey, s_wxyz
    cudaFuncSetAttribute(fps_kernel, cudaFuncAttributeMaxDynamicSharedMemorySize, fps_smem);
    fps_kernel<<<1, 512, fps_smem>>>();

    topk_kernel<<<NS / 8, 256>>>();

    mlp_kernel<<<NS / CPB, 128>>>(W1, b1, W2, b2, out);
    fill_kernel<<<((NPTS - NS) * 128 + 255) / 256, 256>>>(out);
}